// round 3
// baseline (speedup 1.0000x reference)
#include <cuda_runtime.h>
#include <cstdint>

#define BB     64
#define TT_    2000
#define AA     256
#define FF     32
#define KK     31
#define TILE   100
#define NTIL   20
#define NTILES (BB * NTIL)
#define GRID   296
#define NPR    66
#define C2L    2.8853900817779268f   // 2*log2(e)

typedef unsigned long long ull;

// Scratch (no allocations allowed)
__device__ float g_W2s[KK * AA];     // W2 rows 0..30, pre-scaled by C2L
__device__ float g_qadd[AA];         // score_b + conv_b @ loc_w (unscaled)
__device__ float g_energy[BB * TT_];
__device__ int   g_done[BB];         // per-b tile completion counters (self-resetting)
__device__ int   g_bar_cnt;          // grid barrier (sense-reversing, replay-safe)
__device__ int   g_bar_sense;

__device__ __forceinline__ ull pk(float lo, float hi) {
    return ((ull)__float_as_uint(hi) << 32) | (ull)__float_as_uint(lo);
}
#define FMA2(acc, p, w) asm("fma.rn.f32x2 %0, %1, %2, %0;" : "+l"(acc) : "l"(p), "l"(w))

__global__ void __launch_bounds__(256, 2) fused_kernel(
    const float* __restrict__ query,
    const float* __restrict__ pw,
    const float* __restrict__ wmem,
    const int*   __restrict__ lens,
    const float* __restrict__ cw,
    const float* __restrict__ cb,
    const float* __restrict__ lw,
    const float* __restrict__ sv,
    const float* __restrict__ sb,
    float*       __restrict__ out) {

    __shared__ float s_c[FF];
    __shared__ __align__(16) ull Esh[NPR];
    __shared__ float Wsum[8][TILE];
    __shared__ float s_red[8];
    __shared__ float s_m, s_inv;
    __shared__ int   s_flag;

    const int tid = threadIdx.x;
    const int bid = blockIdx.x;
    const int a   = tid;

    // ---------------- Phase 1: W2[k,a] = sum_f cw[k,f]*lw[f,a] (scaled) ----
    if (bid <= KK) {
        if (tid < FF) s_c[tid] = (bid < KK) ? cw[bid * FF + tid] : cb[tid];
        __syncthreads();
        float s = 0.f;
        #pragma unroll
        for (int f = 0; f < FF; ++f) s = fmaf(s_c[f], lw[f * AA + a], s);
        if (bid < KK) g_W2s[bid * AA + a] = s * C2L;
        else          g_qadd[a] = sb[a] + s;
        __threadfence();
    }
    __syncthreads();

    // ---------------- Grid barrier (sense-reversing, replay-safe) ---------
    if (tid == 0) {
        int sns = *(volatile int*)&g_bar_sense;     // read before arrival
        int old = atomicAdd(&g_bar_cnt, 1);
        if (old == GRID - 1) {
            g_bar_cnt = 0;
            __threadfence();
            *(volatile int*)&g_bar_sense = 1 - sns;
        } else {
            while (*(volatile int*)&g_bar_sense == sns) { __nanosleep(32); }
        }
    }
    __syncthreads();
    __threadfence();

    // ---------------- Per-block constants (b-independent, hoisted) --------
    const float qadd = g_qadd[a];
    const float svv  = sv[a];
    // even pairs: (W2[2j], W2[2j+1]); odd pairs: (W2[2j-1], W2[2j]); W2[-1]=W2[31]=0
    ull w2e[16], w2o[16];
    {
        const float* W = g_W2s;
        #pragma unroll
        for (int j = 0; j < 15; ++j)
            w2e[j] = pk(W[(2 * j) * AA + a], W[(2 * j + 1) * AA + a]);
        w2e[15] = pk(W[30 * AA + a], 0.f);
        w2o[0]  = pk(0.f, W[0 * AA + a]);
        #pragma unroll
        for (int j = 1; j < 16; ++j)
            w2o[j] = pk(W[(2 * j - 1) * AA + a], W[(2 * j) * AA + a]);
    }
    const int lane = tid & 31, warp = tid >> 5;

    // ---------------- Phase 2: tiles (+ fused per-b softmax) --------------
    for (int tile = bid; tile < NTILES; tile += GRID) {
        const int b   = tile & 63;
        const int tix = tile >> 6;
        const int len = lens[b];
        const int t0  = tix * TILE;
        if (t0 >= len) continue;                       // fully masked: skip
        const int n   = min(t0 + TILE, len) - t0;
        const int n4  = (n + 3) & ~3;

        // window pairs: Esh[j] = (pw[t0-15+2j], pw[t0-15+2j+1]), zero-padded
        if (tid < 65) {
            int g0 = t0 - 15 + 2 * tid;
            float w0 = (g0     >= 0 && g0     < TT_) ? pw[b * TT_ + g0]     : 0.f;
            float w1 = (g0 + 1 >= 0 && g0 + 1 < TT_) ? pw[b * TT_ + g0 + 1] : 0.f;
            Esh[tid] = pk(w0, w1);
        }
        __syncthreads();

        const float qbp = (query[b * AA + a] + qadd) * C2L;
        const float* xp = wmem + ((size_t)(b * TT_ + t0)) * AA + a;

        for (int tb = 0; tb < n4; tb += 4) {
            const int m0 = tb >> 1;                     // even -> 16B aligned
            float x0 = (tb + 0 < n) ? __ldg(xp)          : 0.f;
            float x1 = (tb + 1 < n) ? __ldg(xp + AA)     : 0.f;
            float x2 = (tb + 2 < n) ? __ldg(xp + 2 * AA) : 0.f;
            float x3 = (tb + 3 < n) ? __ldg(xp + 3 * AA) : 0.f;
            xp += 4 * AA;

            ull a0 = pk(fmaf(x0, C2L, qbp), 0.f);
            ull a1 = pk(fmaf(x1, C2L, qbp), 0.f);
            ull a2 = pk(fmaf(x2, C2L, qbp), 0.f);
            ull a3 = pk(fmaf(x3, C2L, qbp), 0.f);

            const ulonglong2* Ep = (const ulonglong2*)(Esh + m0);
            #pragma unroll
            for (int jj = 0; jj < 8; ++jj) {
                ulonglong2 e = Ep[jj];                  // LDS.128 broadcast
                FMA2(a0, e.x, w2e[2 * jj]);
                FMA2(a1, e.x, w2o[2 * jj]);
                if (jj > 0) {
                    FMA2(a2, e.x, w2e[2 * jj - 1]);
                    FMA2(a3, e.x, w2o[2 * jj - 1]);
                }
                FMA2(a0, e.y, w2e[2 * jj + 1]);
                FMA2(a1, e.y, w2o[2 * jj + 1]);
                FMA2(a2, e.y, w2e[2 * jj]);
                FMA2(a3, e.y, w2o[2 * jj]);
            }
            { ull e16 = Esh[m0 + 16]; FMA2(a2, e16, w2e[15]); FMA2(a3, e16, w2o[15]); }

            // tanh(z) = 1 - 2/(e^{2z}+1); acc already holds 2z*log2(e) split lo/hi
            float p0, p1, p2, p3;
            {
                float arg, u, r;
                #define FIN(acc, dst)                                                   \
                    arg = __uint_as_float((unsigned)(acc)) +                            \
                          __uint_as_float((unsigned)((acc) >> 32));                     \
                    asm("ex2.approx.f32 %0, %1;" : "=f"(u) : "f"(arg));                 \
                    asm("rcp.approx.f32 %0, %1;" : "=f"(r) : "f"(u + 1.0f));            \
                    dst = svv * fmaf(-2.0f, r, 1.0f);
                FIN(a0, p0); FIN(a1, p1); FIN(a2, p2); FIN(a3, p3);
                #undef FIN
            }

            // folded 4-chain warp reduction: 9 shfl instead of 20
            float s0 = p0 + __shfl_xor_sync(0xffffffffu, p0, 16);
            float s1 = p1 + __shfl_xor_sync(0xffffffffu, p1, 16);
            float s2 = p2 + __shfl_xor_sync(0xffffffffu, p2, 16);
            float s3 = p3 + __shfl_xor_sync(0xffffffffu, p3, 16);
            float q0 = (lane < 16) ? s0 : s2;
            float q1 = (lane < 16) ? s1 : s3;
            float u0 = q0 + __shfl_xor_sync(0xffffffffu, q0, 8);
            float u1 = q1 + __shfl_xor_sync(0xffffffffu, q1, 8);
            float v  = (lane & 8) ? u1 : u0;
            v += __shfl_xor_sync(0xffffffffu, v, 4);
            v += __shfl_xor_sync(0xffffffffu, v, 2);
            v += __shfl_xor_sync(0xffffffffu, v, 1);
            if ((lane & 7) == 0) Wsum[warp][tb + (lane >> 3)] = v;
        }
        __syncthreads();
        for (int i = tid; i < n; i += 256) {
            float s = 0.f;
            #pragma unroll
            for (int w = 0; w < 8; ++w) s += Wsum[w][i];
            g_energy[b * TT_ + t0 + i] = s;
        }

        // -------- per-b completion counter; last tile's block runs softmax
        __threadfence();
        __syncthreads();
        const int live = (len + TILE - 1) / TILE;
        if (tid == 0) {
            int old = atomicAdd(&g_done[b], 1);
            s_flag = (old == live - 1);
            if (s_flag) g_done[b] = 0;                 // reset for next replay
        }
        __syncthreads();
        if (s_flag) {
            __threadfence();
            const float* e = g_energy + b * TT_;

            float m = -3.402823466e38f;
            for (int t = tid; t < len; t += 256) m = fmaxf(m, e[t]);
            #pragma unroll
            for (int o = 16; o; o >>= 1) m = fmaxf(m, __shfl_xor_sync(0xffffffffu, m, o));
            if (lane == 0) s_red[warp] = m;
            __syncthreads();
            if (tid < 32) {
                float x = (tid < 8) ? s_red[tid] : -3.402823466e38f;
                #pragma unroll
                for (int o = 4; o; o >>= 1) x = fmaxf(x, __shfl_xor_sync(0xffffffffu, x, o));
                if (tid == 0) s_m = x;
            }
            __syncthreads();
            m = s_m;

            float s = 0.f;
            for (int t = tid; t < len; t += 256) s += __expf(e[t] - m);
            #pragma unroll
            for (int o = 16; o; o >>= 1) s += __shfl_xor_sync(0xffffffffu, s, o);
            if (lane == 0) s_red[warp] = s;
            __syncthreads();
            if (tid < 32) {
                float x = (tid < 8) ? s_red[tid] : 0.f;
                #pragma unroll
                for (int o = 4; o; o >>= 1) x += __shfl_xor_sync(0xffffffffu, x, o);
                if (tid == 0) s_inv = 1.0f / x;
            }
            __syncthreads();
            const float inv = s_inv;

            for (int t = tid; t < TT_; t += 256) {
                float w = (t < len) ? __expf(e[t] - m) * inv : 0.f;
                out[b * TT_ + t] = w;
                out[BB * TT_ + b * TT_ + t] = w + pw[b * TT_ + t];
            }
        }
        __syncthreads();
    }
}

// ---------------------------------------------------------------------------
extern "C" void kernel_launch(void* const* d_in, const int* in_sizes, int n_in,
                              void* d_out, int out_size) {
    const float* query  = (const float*)d_in[0];
    const float* prevw  = (const float*)d_in[1];
    const float* wmem   = (const float*)d_in[2];
    const int*   lens   = (const int*)  d_in[3];
    const float* convw  = (const float*)d_in[4];
    const float* convb  = (const float*)d_in[5];
    const float* locw   = (const float*)d_in[6];
    const float* scorev = (const float*)d_in[7];
    const float* scoreb = (const float*)d_in[8];
    float* out = (float*)d_out;

    fused_kernel<<<GRID, 256>>>(query, prevw, wmem, lens, convw, convb, locw,
                                scorev, scoreb, out);
}

// round 4
// speedup vs baseline: 1.8812x; 1.8812x over previous
#include <cuda_runtime.h>
#include <cstdint>

#define BB     64
#define TT_    2000
#define AA     256
#define FF     32
#define KK     31
#define TILE   100
#define NTIL   20
#define NTILES (BB * NTIL)
#define NPR    66
#define C2L    2.8853900817779268f   // 2*log2(e)

typedef unsigned long long ull;

// Scratch (no allocations allowed)
__device__ float g_W2s[KK * AA];     // W2 rows 0..30, pre-scaled by C2L
__device__ float g_qadd[AA];         // score_b + conv_b @ loc_w (unscaled)
__device__ float g_energy[BB * TT_];
__device__ int   g_w2_done;          // 0 -> 32 within a run; reset by softmax

__device__ __forceinline__ ull pk(float lo, float hi) {
    return ((ull)__float_as_uint(hi) << 32) | (ull)__float_as_uint(lo);
}
#define FMA2(acc, p, w) asm("fma.rn.f32x2 %0, %1, %2, %0;" : "+l"(acc) : "l"(p), "l"(w))

// ---------------------------------------------------------------------------
// Energy kernel (grid NTILES, dynamic HW scheduling).
// Blocks 0..31 first compute one W2 row each (row 31 = bias fold), then all
// blocks process their (b, tile). First-wave blocks overlap prologue with W2.
// ---------------------------------------------------------------------------
__global__ void __launch_bounds__(256, 3) energy_kernel(
    const float* __restrict__ query,
    const float* __restrict__ pw,
    const float* __restrict__ wmem,
    const int*   __restrict__ lens,
    const float* __restrict__ cw,
    const float* __restrict__ cb,
    const float* __restrict__ lw,
    const float* __restrict__ sv,
    const float* __restrict__ sb) {

    __shared__ float s_c[FF];
    __shared__ __align__(16) ull Esh[NPR];
    __shared__ __align__(16) ull Osh[NPR];
    __shared__ float Wsum[8][TILE];

    const int tid  = threadIdx.x;
    const int bid  = blockIdx.x;
    const int a    = tid;
    const int lane = tid & 31, warp = tid >> 5;

    // -------- W2 phase (blocks 0..31 only) --------------------------------
    if (bid < 32) {
        if (tid < FF) s_c[tid] = (bid < KK) ? cw[bid * FF + tid] : cb[tid];
        __syncthreads();
        float s = 0.f;
        #pragma unroll
        for (int f = 0; f < FF; ++f) s = fmaf(s_c[f], lw[f * AA + a], s);
        if (bid < KK) g_W2s[bid * AA + a] = s * C2L;
        else          g_qadd[a] = sb[a] + s;
        __threadfence();
        __syncthreads();
        if (tid == 0) atomicAdd(&g_w2_done, 1);
    }

    // -------- Tile setup (no W2 dependency yet) ---------------------------
    const int b   = bid & 63;
    const int tix = bid >> 6;
    const int len = lens[b];
    const int t0  = tix * TILE;
    if (t0 >= len) return;                       // fully masked: skip
    const int n   = min(t0 + TILE, len) - t0;
    const int n4  = (n + 3) & ~3;

    // window pairs from pw (SAME padding):
    // Esh[j]=(W[2j],W[2j+1])  Osh[j]=(W[2j+1],W[2j+2]),  W[i]=pw[b,t0-15+i]
    if (tid < NPR) {
        const int g0 = t0 - 15 + 2 * tid;
        float w0 = (g0     >= 0 && g0     < TT_) ? pw[b * TT_ + g0]     : 0.f;
        float w1 = (g0 + 1 >= 0 && g0 + 1 < TT_) ? pw[b * TT_ + g0 + 1] : 0.f;
        float w2 = (g0 + 2 >= 0 && g0 + 2 < TT_) ? pw[b * TT_ + g0 + 2] : 0.f;
        Esh[tid] = pk(w0, w1);
        Osh[tid] = pk(w1, w2);
    }
    const float q   = query[b * AA + a];
    const float svv = sv[a];
    const float n2s = -2.0f * svv;

    // -------- Wait for W2 (replay-safe: softmax resets the counter) -------
    if (tid == 0) {
        while (*(volatile int*)&g_w2_done < 32) { __nanosleep(64); }
    }
    __syncthreads();
    __threadfence();

    // Per-thread constants (column 'a'); W2 already scaled by C2L
    const float qbp = (q + g_qadd[a]) * C2L;
    ull w2p[16];
    #pragma unroll
    for (int j = 0; j < 15; ++j)
        w2p[j] = pk(g_W2s[(2 * j) * AA + a], g_W2s[(2 * j + 1) * AA + a]);
    w2p[15] = pk(g_W2s[30 * AA + a], 0.f);

    const float* xp = wmem + ((size_t)(b * TT_ + t0)) * AA + a;

    for (int tb = 0; tb < n4; tb += 4) {
        const int m0 = tb >> 1;                  // even -> 16B-aligned pair base
        float x0 = (tb + 0 < n) ? __ldg(xp)          : 0.f;
        float x1 = (tb + 1 < n) ? __ldg(xp + AA)     : 0.f;
        float x2 = (tb + 2 < n) ? __ldg(xp + 2 * AA) : 0.f;
        float x3 = (tb + 3 < n) ? __ldg(xp + 3 * AA) : 0.f;
        xp += 4 * AA;

        ull a0 = pk(fmaf(x0, C2L, qbp), 0.f);
        ull a1 = pk(fmaf(x1, C2L, qbp), 0.f);
        ull a2 = pk(fmaf(x2, C2L, qbp), 0.f);
        ull a3 = pk(fmaf(x3, C2L, qbp), 0.f);

        const ulonglong2* Ep = (const ulonglong2*)(Esh + m0);
        const ulonglong2* Op = (const ulonglong2*)(Osh + m0);
        #pragma unroll
        for (int m = 0; m < 8; ++m) {
            ulonglong2 e = Ep[m];                // LDS.128 broadcast
            FMA2(a0, e.x, w2p[2 * m]);
            FMA2(a0, e.y, w2p[2 * m + 1]);
            if (m > 0) FMA2(a2, e.x, w2p[2 * m - 1]);
            FMA2(a2, e.y, w2p[2 * m]);
            ulonglong2 o = Op[m];
            FMA2(a1, o.x, w2p[2 * m]);
            FMA2(a1, o.y, w2p[2 * m + 1]);
            if (m > 0) FMA2(a3, o.x, w2p[2 * m - 1]);
            FMA2(a3, o.y, w2p[2 * m]);
        }
        { ull e16 = Esh[m0 + 16]; FMA2(a2, e16, w2p[15]); }
        { ull o16 = Osh[m0 + 16]; FMA2(a3, o16, w2p[15]); }

        // tanh(z) = 1 - 2/(e^{2z}+1); acc holds 2z*log2(e) split lo/hi
        float p0, p1, p2, p3;
        {
            float arg, u, r;
            #define FIN(acc, dst)                                              \
                arg = __uint_as_float((unsigned)(acc)) +                       \
                      __uint_as_float((unsigned)((acc) >> 32));                \
                asm("ex2.approx.f32 %0, %1;" : "=f"(u) : "f"(arg));            \
                asm("rcp.approx.f32 %0, %1;" : "=f"(r) : "f"(u + 1.0f));       \
                dst = fmaf(n2s, r, svv);
            FIN(a0, p0); FIN(a1, p1); FIN(a2, p2); FIN(a3, p3);
            #undef FIN
        }

        // folded 4-chain warp reduction (9 shfl)
        float s0 = p0 + __shfl_xor_sync(0xffffffffu, p0, 16);
        float s1 = p1 + __shfl_xor_sync(0xffffffffu, p1, 16);
        float s2 = p2 + __shfl_xor_sync(0xffffffffu, p2, 16);
        float s3 = p3 + __shfl_xor_sync(0xffffffffu, p3, 16);
        float q0 = (lane < 16) ? s0 : s2;
        float q1 = (lane < 16) ? s1 : s3;
        float u0 = q0 + __shfl_xor_sync(0xffffffffu, q0, 8);
        float u1 = q1 + __shfl_xor_sync(0xffffffffu, q1, 8);
        float v  = (lane & 8) ? u1 : u0;
        v += __shfl_xor_sync(0xffffffffu, v, 4);
        v += __shfl_xor_sync(0xffffffffu, v, 2);
        v += __shfl_xor_sync(0xffffffffu, v, 1);
        if ((lane & 7) == 0) Wsum[warp][tb + (lane >> 3)] = v;
    }
    __syncthreads();
    for (int i = tid; i < n; i += 256) {
        float s = 0.f;
        #pragma unroll
        for (int w = 0; w < 8; ++w) s += Wsum[w][i];
        g_energy[b * TT_ + t0 + i] = s;
    }
}

// ---------------------------------------------------------------------------
// Softmax per b over t < len; masked entries exact 0 (matches reference:
// exp(MASK_VAL - max) flushes to 0 in fp32). Also resets g_w2_done.
// ---------------------------------------------------------------------------
__global__ __launch_bounds__(512) void softmax_kernel(
    const float* __restrict__ pw,
    const int*   __restrict__ lens,
    float*       __restrict__ out) {

    __shared__ float red[16];
    __shared__ float s_m, s_inv;
    const int b = blockIdx.x, tid = threadIdx.x;
    const int lane = tid & 31, warp = tid >> 5;
    const int len = lens[b];
    const float* e = g_energy + b * TT_;

    if (b == 0 && tid == 0) g_w2_done = 0;   // reset for next graph replay

    float m = -3.402823466e38f;
    for (int t = tid; t < len; t += 512) m = fmaxf(m, e[t]);
    #pragma unroll
    for (int o = 16; o; o >>= 1) m = fmaxf(m, __shfl_xor_sync(0xffffffffu, m, o));
    if (lane == 0) red[warp] = m;
    __syncthreads();
    if (tid < 32) {
        float v = (tid < 16) ? red[tid] : -3.402823466e38f;
        #pragma unroll
        for (int o = 8; o; o >>= 1) v = fmaxf(v, __shfl_xor_sync(0xffffffffu, v, o));
        if (tid == 0) s_m = v;
    }
    __syncthreads();
    m = s_m;

    float s = 0.f;
    for (int t = tid; t < len; t += 512) s += __expf(e[t] - m);
    #pragma unroll
    for (int o = 16; o; o >>= 1) s += __shfl_xor_sync(0xffffffffu, s, o);
    if (lane == 0) red[warp] = s;
    __syncthreads();
    if (tid < 32) {
        float v = (tid < 16) ? red[tid] : 0.f;
        #pragma unroll
        for (int o = 8; o; o >>= 1) v += __shfl_xor_sync(0xffffffffu, v, o);
        if (tid == 0) s_inv = 1.0f / v;
    }
    __syncthreads();
    const float inv = s_inv;

    for (int t = tid; t < TT_; t += 512) {
        float w = (t < len) ? __expf(e[t] - m) * inv : 0.f;
        out[b * TT_ + t] = w;
        out[BB * TT_ + b * TT_ + t] = w + pw[b * TT_ + t];
    }
}

// ---------------------------------------------------------------------------
extern "C" void kernel_launch(void* const* d_in, const int* in_sizes, int n_in,
                              void* d_out, int out_size) {
    const float* query  = (const float*)d_in[0];
    const float* prevw  = (const float*)d_in[1];
    const float* wmem   = (const float*)d_in[2];
    const int*   lens   = (const int*)  d_in[3];
    const float* convw  = (const float*)d_in[4];
    const float* convb  = (const float*)d_in[5];
    const float* locw   = (const float*)d_in[6];
    const float* scorev = (const float*)d_in[7];
    const float* scoreb = (const float*)d_in[8];
    float* out = (float*)d_out;

    energy_kernel<<<NTILES, 256>>>(query, prevw, wmem, lens, convw, convb, locw,
                                   scorev, scoreb);
    softmax_kernel<<<BB, 512>>>(prevw, lens, out);
}

// round 6
// speedup vs baseline: 1.8954x; 1.0075x over previous
#include <cuda_runtime.h>
#include <cstdint>

#define BB     64
#define TT_    2000
#define AA     256
#define FF     32
#define KK     31
#define TILE   100
#define NTIL   20
#define NTILES (BB * NTIL)
#define NPR    66
#define SPLIT  8
#define SLICE  (TT_ / SPLIT)         // 250
#define C2L    2.8853900817779268f   // 2*log2(e)
#define NEGINF (-3.402823466e38f)

typedef unsigned long long ull;

// Scratch (no allocations allowed)
__device__ float g_W2s[KK * AA];     // W2 rows 0..30, pre-scaled by C2L
__device__ float g_qadd[AA];         // score_b + conv_b @ loc_w
__device__ float g_energy[BB * TT_];
__device__ float g_pmax[NTILES];     // per-tile max   [b * NTIL + tix]
__device__ float g_psum[NTILES];     // per-tile sum   [b * NTIL + tix]
__device__ int   g_w2_done;          // 0 -> 32 within a run; reset by normalize

__device__ __forceinline__ ull pk(float lo, float hi) {
    return ((ull)__float_as_uint(hi) << 32) | (ull)__float_as_uint(lo);
}
#define FMA2(acc, p, w) asm("fma.rn.f32x2 %0, %1, %2, %0;" : "+l"(acc) : "l"(p), "l"(w))

// ---------------------------------------------------------------------------
// Energy kernel (grid NTILES, dynamic HW scheduling).
// Blocks 0..31 first compute one W2 row each (row 31 = bias fold), then all
// blocks process their (b, tile) and emit per-tile softmax partials.
// ---------------------------------------------------------------------------
__global__ void __launch_bounds__(256, 3) energy_kernel(
    const float* __restrict__ query,
    const float* __restrict__ pw,
    const float* __restrict__ wmem,
    const int*   __restrict__ lens,
    const float* __restrict__ cw,
    const float* __restrict__ cb,
    const float* __restrict__ lw,
    const float* __restrict__ sv,
    const float* __restrict__ sb) {

    __shared__ float s_c[FF];
    __shared__ __align__(16) ull Esh[NPR];
    __shared__ __align__(16) ull Osh[NPR];
    __shared__ float Wsum[8][TILE];
    __shared__ float s_red[8];
    __shared__ float s_m;

    const int tid  = threadIdx.x;
    const int bid  = blockIdx.x;
    const int a    = tid;
    const int lane = tid & 31, warp = tid >> 5;

    // -------- W2 phase (blocks 0..31 only) --------------------------------
    if (bid < 32) {
        if (tid < FF) s_c[tid] = (bid < KK) ? cw[bid * FF + tid] : cb[tid];
        __syncthreads();
        float s = 0.f;
        #pragma unroll
        for (int f = 0; f < FF; ++f) s = fmaf(s_c[f], lw[f * AA + a], s);
        if (bid < KK) g_W2s[bid * AA + a] = s * C2L;
        else          g_qadd[a] = sb[a] + s;
        __threadfence();
        __syncthreads();
        if (tid == 0) atomicAdd(&g_w2_done, 1);
    }

    // -------- Tile setup (no W2 dependency yet) ---------------------------
    const int b   = bid & 63;
    const int tix = bid >> 6;
    const int len = lens[b];
    const int t0  = tix * TILE;
    if (t0 >= len) return;                       // fully masked: skip
    const int n   = min(t0 + TILE, len) - t0;
    const int n4  = (n + 3) & ~3;

    // window pairs from pw (SAME padding):
    // Esh[j]=(W[2j],W[2j+1])  Osh[j]=(W[2j+1],W[2j+2]),  W[i]=pw[b,t0-15+i]
    if (tid < NPR) {
        const int g0 = t0 - 15 + 2 * tid;
        float w0 = (g0     >= 0 && g0     < TT_) ? pw[b * TT_ + g0]     : 0.f;
        float w1 = (g0 + 1 >= 0 && g0 + 1 < TT_) ? pw[b * TT_ + g0 + 1] : 0.f;
        float w2 = (g0 + 2 >= 0 && g0 + 2 < TT_) ? pw[b * TT_ + g0 + 2] : 0.f;
        Esh[tid] = pk(w0, w1);
        Osh[tid] = pk(w1, w2);
    }
    const float q   = query[b * AA + a];
    const float svv = sv[a];
    const float n2s = -2.0f * svv;

    // -------- Wait for W2 (replay-safe: normalize resets the counter) -----
    if (tid == 0) {
        while (*(volatile int*)&g_w2_done < 32) { __nanosleep(64); }
    }
    __syncthreads();
    __threadfence();

    // Per-thread constants (column 'a'); W2 already scaled by C2L
    const float qbp = (q + g_qadd[a]) * C2L;
    ull w2p[16];
    #pragma unroll
    for (int j = 0; j < 15; ++j)
        w2p[j] = pk(g_W2s[(2 * j) * AA + a], g_W2s[(2 * j + 1) * AA + a]);
    w2p[15] = pk(g_W2s[30 * AA + a], 0.f);

    const float* xp = wmem + ((size_t)(b * TT_ + t0)) * AA + a;

    for (int tb = 0; tb < n4; tb += 4) {
        const int m0 = tb >> 1;                  // even -> 16B-aligned pair base
        float x0 = (tb + 0 < n) ? __ldg(xp)          : 0.f;
        float x1 = (tb + 1 < n) ? __ldg(xp + AA)     : 0.f;
        float x2 = (tb + 2 < n) ? __ldg(xp + 2 * AA) : 0.f;
        float x3 = (tb + 3 < n) ? __ldg(xp + 3 * AA) : 0.f;
        xp += 4 * AA;

        ull a0 = pk(fmaf(x0, C2L, qbp), 0.f);
        ull a1 = pk(fmaf(x1, C2L, qbp), 0.f);
        ull a2 = pk(fmaf(x2, C2L, qbp), 0.f);
        ull a3 = pk(fmaf(x3, C2L, qbp), 0.f);

        const ulonglong2* Ep = (const ulonglong2*)(Esh + m0);
        const ulonglong2* Op = (const ulonglong2*)(Osh + m0);
        #pragma unroll
        for (int m = 0; m < 8; ++m) {
            ulonglong2 e = Ep[m];                // LDS.128 broadcast
            FMA2(a0, e.x, w2p[2 * m]);
            FMA2(a0, e.y, w2p[2 * m + 1]);
            if (m > 0) FMA2(a2, e.x, w2p[2 * m - 1]);
            FMA2(a2, e.y, w2p[2 * m]);
            ulonglong2 o = Op[m];
            FMA2(a1, o.x, w2p[2 * m]);
            FMA2(a1, o.y, w2p[2 * m + 1]);
            if (m > 0) FMA2(a3, o.x, w2p[2 * m - 1]);
            FMA2(a3, o.y, w2p[2 * m]);
        }
        { ull e16 = Esh[m0 + 16]; FMA2(a2, e16, w2p[15]); }
        { ull o16 = Osh[m0 + 16]; FMA2(a3, o16, w2p[15]); }

        // tanh(z) = 1 - 2/(e^{2z}+1); acc holds 2z*log2(e) split lo/hi
        float p0, p1, p2, p3;
        {
            float arg, u, r;
            #define FIN(acc, dst)                                              \
                arg = __uint_as_float((unsigned)(acc)) +                       \
                      __uint_as_float((unsigned)((acc) >> 32));                \
                asm("ex2.approx.f32 %0, %1;" : "=f"(u) : "f"(arg));            \
                asm("rcp.approx.f32 %0, %1;" : "=f"(r) : "f"(u + 1.0f));       \
                dst = fmaf(n2s, r, svv);
            FIN(a0, p0); FIN(a1, p1); FIN(a2, p2); FIN(a3, p3);
            #undef FIN
        }

        // folded 4-chain warp reduction (9 shfl)
        float s0 = p0 + __shfl_xor_sync(0xffffffffu, p0, 16);
        float s1 = p1 + __shfl_xor_sync(0xffffffffu, p1, 16);
        float s2 = p2 + __shfl_xor_sync(0xffffffffu, p2, 16);
        float s3 = p3 + __shfl_xor_sync(0xffffffffu, p3, 16);
        float q0 = (lane < 16) ? s0 : s2;
        float q1 = (lane < 16) ? s1 : s3;
        float u0 = q0 + __shfl_xor_sync(0xffffffffu, q0, 8);
        float u1 = q1 + __shfl_xor_sync(0xffffffffu, q1, 8);
        float v  = (lane & 8) ? u1 : u0;
        v += __shfl_xor_sync(0xffffffffu, v, 4);
        v += __shfl_xor_sync(0xffffffffu, v, 2);
        v += __shfl_xor_sync(0xffffffffu, v, 1);
        if ((lane & 7) == 0) Wsum[warp][tb + (lane >> 3)] = v;
    }
    __syncthreads();

    // -------- Epilogue: write energies + per-tile softmax partials --------
    float e_val = NEGINF;
    if (tid < n) {
        float s = 0.f;
        #pragma unroll
        for (int w = 0; w < 8; ++w) s += Wsum[w][tid];
        g_energy[b * TT_ + t0 + tid] = s;
        e_val = s;
    }
    // block max over e_val
    float m = e_val;
    #pragma unroll
    for (int o = 16; o; o >>= 1) m = fmaxf(m, __shfl_xor_sync(0xffffffffu, m, o));
    if (lane == 0) s_red[warp] = m;
    __syncthreads();
    if (tid < 32) {
        float v = (tid < 8) ? s_red[tid] : NEGINF;
        #pragma unroll
        for (int o = 4; o; o >>= 1) v = fmaxf(v, __shfl_xor_sync(0xffffffffu, v, o));
        if (tid == 0) s_m = v;
    }
    __syncthreads();
    const float tmax = s_m;
    // block sum of exp(e - tmax)
    float es = (tid < n) ? __expf(e_val - tmax) : 0.f;
    #pragma unroll
    for (int o = 16; o; o >>= 1) es += __shfl_xor_sync(0xffffffffu, es, o);
    if (lane == 0) s_red[warp] = es;
    __syncthreads();
    if (tid == 0) {
        float v = 0.f;
        #pragma unroll
        for (int w = 0; w < 8; ++w) v += s_red[w];
        g_pmax[b * NTIL + tix] = tmax;     // layout matches normalize_kernel
        g_psum[b * NTIL + tix] = v;
    }
}

// ---------------------------------------------------------------------------
// Normalize: grid (SPLIT, BB). Each block combines the <=NTIL tile partials
// for its b (redundantly, cheap) and writes a 250-element slice of both
// outputs. Masked entries exact 0 (matches reference: exp(MASK_VAL - max)
// flushes to 0 in fp32).
// ---------------------------------------------------------------------------
__global__ __launch_bounds__(256) void normalize_kernel(
    const float* __restrict__ pw,
    const int*   __restrict__ lens,
    float*       __restrict__ out) {

    const int b    = blockIdx.y;
    const int sl   = blockIdx.x;
    const int tid  = threadIdx.x;
    const int len  = lens[b];
    const int live = (len + TILE - 1) / TILE;

    if (b == 0 && sl == 0 && tid == 0) g_w2_done = 0;   // reset for replay

    // Combine tile partials: M = max, S = sum s_i * exp(m_i - M)
    float M = NEGINF;
    #pragma unroll 4
    for (int i = 0; i < live; ++i) M = fmaxf(M, g_pmax[b * NTIL + i]);
    float S = 0.f;
    #pragma unroll 4
    for (int i = 0; i < live; ++i)
        S += g_psum[b * NTIL + i] * __expf(g_pmax[b * NTIL + i] - M);
    const float inv = 1.0f / S;

    const int t0 = sl * SLICE;
    const float* e = g_energy + b * TT_;
    for (int t = t0 + tid; t < t0 + SLICE; t += 256) {
        float w = (t < len) ? __expf(e[t] - M) * inv : 0.f;
        out[b * TT_ + t] = w;
        out[BB * TT_ + b * TT_ + t] = w + pw[b * TT_ + t];
    }
}

// ---------------------------------------------------------------------------
extern "C" void kernel_launch(void* const* d_in, const int* in_sizes, int n_in,
                              void* d_out, int out_size) {
    const float* query  = (const float*)d_in[0];
    const float* prevw  = (const float*)d_in[1];
    const float* wmem   = (const float*)d_in[2];
    const int*   lens   = (const int*)  d_in[3];
    const float* convw  = (const float*)d_in[4];
    const float* convb  = (const float*)d_in[5];
    const float* locw   = (const float*)d_in[6];
    const float* scorev = (const float*)d_in[7];
    const float* scoreb = (const float*)d_in[8];
    float* out = (float*)d_out;

    energy_kernel<<<NTILES, 256>>>(query, prevw, wmem, lens, convw, convb, locw,
                                   scorev, scoreb);
    normalize_kernel<<<dim3(SPLIT, BB), 256>>>(prevw, lens, out);
}